// round 1
// baseline (speedup 1.0000x reference)
#include <cuda_runtime.h>
#include <math.h>

#define BATCH 4
#define SEQ 2048
#define DM 1024
#define DI 2048
#define NS 16
#define ROWS (BATCH*SEQ)   /* 8192 */

// ---------------- scratch (static device allocations; no cudaMalloc) -------
__device__ float g_xz [ (size_t)ROWS * (2*DI) ];   // in_proj output: [x_inner | z]
__device__ float g_xc [ (size_t)ROWS * DI ];       // conv+silu output
__device__ float g_bdt[ (size_t)ROWS * (2*NS) ];   // [B_p | C_p]
__device__ float g_dt [ (size_t)ROWS * DI ];       // softplus(xc@W_dt + b)
__device__ float g_yz [ (size_t)ROWS * DI ];       // gated scan output

// ---------------- generic 128x128x8 fp32 GEMM, row-major ------------------
// C[M,N] = A[M,K] @ B[K,N].  EPI==0: plain store. EPI==1: softplus(v + bias[n]).
template<int EPI>
__global__ void __launch_bounds__(256) sgemm128(const float* __restrict__ A,
                                                const float* __restrict__ B,
                                                float* __restrict__ C,
                                                int M, int N, int K,
                                                const float* __restrict__ bias)
{
    __shared__ float As[8][128];
    __shared__ float Bs[8][128];

    const int tid = threadIdx.x;
    const int bm  = blockIdx.y, bn = blockIdx.x;

    const int a_row = tid >> 1;          // 0..127
    const int a_col = (tid & 1) * 4;     // 0 or 4
    const int b_row = tid >> 5;          // 0..7
    const int b_col = (tid & 31) * 4;    // 0..124

    const float* Ag = A + (size_t)(bm*128 + a_row)*K + a_col;
    const float* Bg = B + (size_t)b_row*N + bn*128 + b_col;

    const int tx = tid & 15, ty = tid >> 4;   // 16x16 thread grid, 8x8 each

    float acc[8][8];
#pragma unroll
    for (int i = 0; i < 8; i++)
#pragma unroll
        for (int j = 0; j < 8; j++) acc[i][j] = 0.f;

    float4 av = *(const float4*)Ag;
    float4 bv = *(const float4*)Bg;

    for (int k0 = 0; k0 < K; k0 += 8) {
        // stage current tile
        As[a_col+0][a_row] = av.x;
        As[a_col+1][a_row] = av.y;
        As[a_col+2][a_row] = av.z;
        As[a_col+3][a_row] = av.w;
        *(float4*)&Bs[b_row][b_col] = bv;
        __syncthreads();

        // prefetch next tile (overlap with compute)
        if (k0 + 8 < K) {
            Ag += 8; Bg += (size_t)8*N;
            av = *(const float4*)Ag;
            bv = *(const float4*)Bg;
        }

#pragma unroll
        for (int kk = 0; kk < 8; kk++) {
            float4 a0 = *(const float4*)&As[kk][ty*8];
            float4 a1 = *(const float4*)&As[kk][ty*8+4];
            float4 b0 = *(const float4*)&Bs[kk][tx*8];
            float4 b1 = *(const float4*)&Bs[kk][tx*8+4];
            float am[8] = {a0.x,a0.y,a0.z,a0.w,a1.x,a1.y,a1.z,a1.w};
            float bb[8] = {b0.x,b0.y,b0.z,b0.w,b1.x,b1.y,b1.z,b1.w};
#pragma unroll
            for (int i = 0; i < 8; i++)
#pragma unroll
                for (int j = 0; j < 8; j++)
                    acc[i][j] += am[i]*bb[j];
        }
        __syncthreads();
    }

    const int crow = bm*128 + ty*8;
    const int ccol = bn*128 + tx*8;
#pragma unroll
    for (int i = 0; i < 8; i++) {
        float out[8];
#pragma unroll
        for (int j = 0; j < 8; j++) {
            float v = acc[i][j];
            if (EPI == 1) {
                v += bias[ccol + j];
                v = (v > 20.f) ? v : log1pf(__expf(v));   // softplus
            }
            out[j] = v;
        }
        float* Cp = C + (size_t)(crow + i)*N + ccol;
        *(float4*)(Cp)     = make_float4(out[0],out[1],out[2],out[3]);
        *(float4*)(Cp + 4) = make_float4(out[4],out[5],out[6],out[7]);
    }
}

// ---------------- causal depthwise conv (K=4) + SiLU ----------------------
// x_inner lives in g_xz columns [0, DI). Output -> g_xc.
__global__ void __launch_bounds__(256) conv_silu_kernel(const float* __restrict__ cw,
                                                        const float* __restrict__ cb)
{
    const int d  = blockIdx.x*256 + threadIdx.x;  // 0..DI-1
    const int l0 = blockIdx.y * 8;                // chunk of 8 timesteps
    const int b  = blockIdx.z;

    const float w0 = cw[d*4+0], w1 = cw[d*4+1], w2 = cw[d*4+2], w3 = cw[d*4+3];
    const float bb = cb[d];

    const float* xin = g_xz + (size_t)(b*SEQ)*(2*DI) + d;
    float* out       = g_xc + (size_t)(b*SEQ + l0)*DI + d;

    float win0, win1, win2;
    {
        int l = l0 - 3; win0 = (l >= 0) ? xin[(size_t)l*(2*DI)] : 0.f;
        l = l0 - 2;     win1 = (l >= 0) ? xin[(size_t)l*(2*DI)] : 0.f;
        l = l0 - 1;     win2 = (l >= 0) ? xin[(size_t)l*(2*DI)] : 0.f;
    }
#pragma unroll
    for (int i = 0; i < 8; i++) {
        float cur = xin[(size_t)(l0 + i)*(2*DI)];
        float v = w0*win0 + w1*win1 + w2*win2 + w3*cur + bb;
        out[(size_t)i*DI] = v / (1.f + __expf(-v));   // silu
        win0 = win1; win1 = win2; win2 = cur;
    }
}

// ---------------- small-N GEMM: bdt = xc @ W_x (N=32) ---------------------
// one warp per output row; lane = output column.
__global__ void __launch_bounds__(256) bdt_kernel(const float* __restrict__ Wx)
{
    const int warp = (blockIdx.x*blockDim.x + threadIdx.x) >> 5;
    const int lane = threadIdx.x & 31;
    if (warp >= ROWS) return;

    const float* xr = g_xc + (size_t)warp*DI;
    float acc = 0.f;
    for (int k = 0; k < DI; k += 8) {
#pragma unroll
        for (int u = 0; u < 8; u++)
            acc += xr[k+u] * Wx[(k+u)*32 + lane];
    }
    g_bdt[(size_t)warp*32 + lane] = acc;
}

// ---------------- selective scan + skip + gating ---------------------------
// 4 threads per channel, 4 states per thread. Fuses y = scan + xc*D, then
// yz = y * silu(z) so GEMM4 reads one buffer.
__global__ void __launch_bounds__(128) scan_kernel(const float* __restrict__ A_log,
                                                   const float* __restrict__ Dp)
{
    const int b    = blockIdx.x;            // 0..3
    const int dblk = blockIdx.y;            // 0..63
    const int tid  = threadIdx.x;           // 0..127
    const int c    = tid >> 2;              // channel within block (0..31)
    const int s    = tid & 3;               // state-group (0..3)
    const int d    = dblk*32 + c;

    float4 Al = *(const float4*)&A_log[(size_t)d*NS + s*4];
    const float A0 = -__expf(Al.x), A1 = -__expf(Al.y),
                A2 = -__expf(Al.z), A3 = -__expf(Al.w);
    const float Dpar = Dp[d];

    const size_t r0 = (size_t)b*SEQ;
    const float* dtp = g_dt  + r0*DI       + d;
    const float* xp  = g_xc  + r0*DI       + d;
    const float* zp  = g_xz  + r0*(2*DI)   + DI + d;
    const float* Bp  = g_bdt + r0*(2*NS)   + s*4;
    const float* Cp  = Bp + NS;
    float*       yp  = g_yz  + r0*DI       + d;

    float h0=0.f, h1=0.f, h2=0.f, h3=0.f;

    // prefetch t=0 inputs
    float  dt_v = *dtp, x_v = *xp, z_v = *zp;
    float4 Bv = *(const float4*)Bp;
    float4 Cv = *(const float4*)Cp;

    for (int t = 0; t < SEQ; t++) {
        const float  dt_c = dt_v, x_c = x_v, z_c = z_v;
        const float4 B_c = Bv, C_c = Cv;
        if (t + 1 < SEQ) {   // prefetch next step (independent of h)
            dtp += DI; xp += DI; zp += 2*DI; Bp += 2*NS; Cp += 2*NS;
            dt_v = *dtp; x_v = *xp; z_v = *zp;
            Bv = *(const float4*)Bp; Cv = *(const float4*)Cp;
        }

        const float dx = dt_c * x_c;
        const float e0 = __expf(dt_c*A0);
        const float e1 = __expf(dt_c*A1);
        const float e2 = __expf(dt_c*A2);
        const float e3 = __expf(dt_c*A3);
        h0 = e0*h0 + dx*B_c.x;
        h1 = e1*h1 + dx*B_c.y;
        h2 = e2*h2 + dx*B_c.z;
        h3 = e3*h3 + dx*B_c.w;

        float y = h0*C_c.x + h1*C_c.y + h2*C_c.z + h3*C_c.w;
        y += __shfl_down_sync(0xffffffffu, y, 2, 4);
        y += __shfl_down_sync(0xffffffffu, y, 1, 4);

        if (s == 0) {
            const float yy = y + x_c*Dpar;
            const float g  = z_c / (1.f + __expf(-z_c));  // silu(z)
            yp[0] = yy * g;
        }
        yp += DI;
    }
}

// ---------------------------------------------------------------------------
extern "C" void kernel_launch(void* const* d_in, const int* in_sizes, int n_in,
                              void* d_out, int out_size)
{
    const float* x      = (const float*)d_in[0];
    const float* W_in   = (const float*)d_in[1];
    const float* conv_w = (const float*)d_in[2];
    const float* conv_b = (const float*)d_in[3];
    const float* W_x    = (const float*)d_in[4];
    const float* W_dt   = (const float*)d_in[5];
    const float* b_dt   = (const float*)d_in[6];
    const float* W_out  = (const float*)d_in[7];
    const float* A_log  = (const float*)d_in[8];
    const float* D_par  = (const float*)d_in[9];
    float* out = (float*)d_out;

    float *xz, *xc, *dt, *yz;
    cudaGetSymbolAddress((void**)&xz, g_xz);
    cudaGetSymbolAddress((void**)&xc, g_xc);
    cudaGetSymbolAddress((void**)&dt, g_dt);
    cudaGetSymbolAddress((void**)&yz, g_yz);

    // 1) xz = x @ W_in            (8192 x 1024 x 4096)
    sgemm128<0><<<dim3((2*DI)/128, ROWS/128), 256>>>(x, W_in, xz, ROWS, 2*DI, DM, nullptr);

    // 2) xc = silu(causal_dwconv(x_inner))
    conv_silu_kernel<<<dim3(DI/256, SEQ/8, BATCH), 256>>>(conv_w, conv_b);

    // 3) bdt = xc @ W_x           (N = 32)
    bdt_kernel<<<ROWS/8, 256>>>(W_x);

    // 4) dt = softplus(xc @ W_dt + b_dt)   (8192 x 2048 x 2048)
    sgemm128<1><<<dim3(DI/128, ROWS/128), 256>>>(xc, W_dt, dt, ROWS, DI, DI, b_dt);

    // 5) selective scan + skip + gating -> yz
    scan_kernel<<<dim3(BATCH, DI/32), 128>>>(A_log, D_par);

    // 6) out = yz @ W_out          (8192 x 2048 x 1024)
    sgemm128<0><<<dim3(DM/128, ROWS/128), 256>>>(yz, W_out, out, ROWS, DM, DI, nullptr);
}

// round 3
// speedup vs baseline: 2.8160x; 2.8160x over previous
#include <cuda_runtime.h>
#include <cuda_bf16.h>
#include <stdint.h>
#include <math.h>

#define BATCH 4
#define SEQ 2048
#define DM 1024
#define DI 2048
#define NS 16
#define ROWS (BATCH*SEQ)   /* 8192 */

// ---------------- scratch (static device arrays; no cudaMalloc) ------------
__device__ float g_xz [(size_t)ROWS*(2*DI)];   // in_proj output [x_inner | z]
__device__ float g_xc [(size_t)ROWS*DI];       // conv+silu output (fp32)
__device__ float g_bdt[(size_t)ROWS*(2*NS)];   // [B | C]
__device__ float g_dt [(size_t)ROWS*DI];       // softplus(xc@W_dt + b)

// bf16 split activations
__device__ __nv_bfloat16 g_xh  [(size_t)ROWS*DM],  g_xl  [(size_t)ROWS*DM];
__device__ __nv_bfloat16 g_xch [(size_t)ROWS*DI],  g_xcl [(size_t)ROWS*DI];
__device__ __nv_bfloat16 g_yzh [(size_t)ROWS*DI],  g_yzl [(size_t)ROWS*DI];
// bf16 split transposed weights [N, K]
__device__ __nv_bfloat16 g_winh [(size_t)(2*DI)*DM], g_winl [(size_t)(2*DI)*DM];
__device__ __nv_bfloat16 g_wdth [(size_t)DI*DI],     g_wdtl [(size_t)DI*DI];
__device__ __nv_bfloat16 g_wouth[(size_t)DM*DI],     g_woutl[(size_t)DM*DI];

// ====================== PTX helpers =======================================
__device__ __forceinline__ uint32_t smem_u32(const void* p){
    return (uint32_t)__cvta_generic_to_shared(p);
}
__device__ __forceinline__ void cp16(void* s, const void* g){
    uint32_t sa = smem_u32(s);
    asm volatile("cp.async.cg.shared.global [%0], [%1], 16;" :: "r"(sa), "l"(g) : "memory");
}
__device__ __forceinline__ void cp_commit(){ asm volatile("cp.async.commit_group;" ::: "memory"); }
template<int N> __device__ __forceinline__ void cp_wait(){ asm volatile("cp.async.wait_group %0;" :: "n"(N) : "memory"); }

#define SWZ(o) ((o) ^ (((o)>>3)&0x70))

#define LDSM4(r0,r1,r2,r3,addr) \
    asm volatile("ldmatrix.sync.aligned.m8n8.x4.shared.b16 {%0,%1,%2,%3}, [%4];" \
        : "=r"(r0),"=r"(r1),"=r"(r2),"=r"(r3) : "r"(addr))

#define MMA_BF16(c, a, b) \
    asm volatile("mma.sync.aligned.m16n8k16.row.col.f32.bf16.bf16.f32 " \
        "{%0,%1,%2,%3},{%4,%5,%6,%7},{%8,%9},{%0,%1,%2,%3};" \
        : "+f"((c)[0]),"+f"((c)[1]),"+f"((c)[2]),"+f"((c)[3]) \
        : "r"((a)[0]),"r"((a)[1]),"r"((a)[2]),"r"((a)[3]),"r"((b)[0]),"r"((b)[1]))

// ====================== HMMA bf16-split GEMM ===============================
// C[M,N] = (Ah+Al)[M,K] @ (Bh+Bl)[N,K]^T   (B row-major [N,K])
// acc = Ah*Bh + Ah*Bl + Al*Bh  (fp32 accumulate).  EPI==1: softplus(v+bias[n]).
static const int T_AH = 0, T_AL = 16384, T_BH = 32768, T_BL = 49152;
static const int STG  = 65536;       // one stage: 4 tiles x 16KB
static const int NSTG = 3;
static const int SMEM_GEMM = NSTG*STG;   // 196608

template<int EPI>
__global__ void __launch_bounds__(256,1)
gemm_mma(const __nv_bfloat16* __restrict__ Ah, const __nv_bfloat16* __restrict__ Al,
         const __nv_bfloat16* __restrict__ Bh, const __nv_bfloat16* __restrict__ Bl,
         float* __restrict__ C, int M, int N, int K, const float* __restrict__ bias)
{
    extern __shared__ char smem[];
    const uint32_t sb = smem_u32(smem);
    const int tid = threadIdx.x, wid = tid>>5, lane = tid&31;
    const int bm = blockIdx.y, bn = blockIdx.x;
    const int wm = wid & 3, wn = wid >> 2;     // warp tile: rows wm*32, cols wn*64

    const __nv_bfloat16* gsrc[4] = {
        Ah + (size_t)(bm*128)*K, Al + (size_t)(bm*128)*K,
        Bh + (size_t)(bn*128)*K, Bl + (size_t)(bn*128)*K };

    const int nk = K/64;

    // loader indices: 1024 chunks of 16B per tile; thread does 4
    const int lrr[4] = { (tid+0)>>3, (tid+256)>>3, (tid+512)>>3, (tid+768)>>3 };
    const int lcc    = tid & 7;

    auto load_stage = [&](int stage, int c0){
        char* dst = smem + stage*STG;
        const size_t coff = (size_t)c0*64;
#pragma unroll
        for (int t = 0; t < 4; t++){
            const __nv_bfloat16* g = gsrc[t] + coff;
            char* st = dst + t*16384;
#pragma unroll
            for (int j = 0; j < 4; j++){
                int rr = lrr[j];
                cp16(st + SWZ((rr<<7) + (lcc<<4)), g + (size_t)rr*K + lcc*8);
            }
        }
        cp_commit();
    };

    float acc[2][8][4];
#pragma unroll
    for (int mt=0; mt<2; mt++)
#pragma unroll
        for (int nt=0; nt<8; nt++)
#pragma unroll
            for (int j=0; j<4; j++) acc[mt][nt][j] = 0.f;

    // lane-derived ldmatrix row/col pieces
    const int lr = lane & 7;
    const int a_row0 = wm*32 + ((lane>>3)&1)*8 + lr;      // + mt*16
    const int a_coff = (lane>>4)*16;                      // byte offset of k-half
    const int b_row0 = wn*64 + (lane>>4)*8 + lr;          // + np*16
    const int b_coff = ((lane>>3)&1)*16;

    load_stage(0, 0);
    if (nk > 1) load_stage(1, 1);

    for (int k0 = 0; k0 < nk; k0++){
        if (k0+2 < nk){ load_stage((k0+2)%NSTG, k0+2); cp_wait<2>(); }
        else if (k0+1 < nk){ cp_wait<1>(); }
        else { cp_wait<0>(); }
        __syncthreads();

        const uint32_t st = sb + (k0%NSTG)*STG;
        const uint32_t aH = st + T_AH, aL = st + T_AL;
        const uint32_t bH = st + T_BH, bL = st + T_BL;

#pragma unroll
        for (int kk = 0; kk < 4; kk++){
            uint32_t ah[2][4], al[2][4], bh[8][2], bl[8][2];
#pragma unroll
            for (int mt = 0; mt < 2; mt++){
                uint32_t off = SWZ(((a_row0 + mt*16)<<7) + kk*32 + a_coff);
                LDSM4(ah[mt][0],ah[mt][1],ah[mt][2],ah[mt][3], aH + off);
                LDSM4(al[mt][0],al[mt][1],al[mt][2],al[mt][3], aL + off);
            }
#pragma unroll
            for (int np = 0; np < 4; np++){
                uint32_t off = SWZ(((b_row0 + np*16)<<7) + kk*32 + b_coff);
                LDSM4(bh[np*2][0],bh[np*2][1],bh[np*2+1][0],bh[np*2+1][1], bH + off);
                LDSM4(bl[np*2][0],bl[np*2][1],bl[np*2+1][0],bl[np*2+1][1], bL + off);
            }
#pragma unroll
            for (int nt = 0; nt < 8; nt++){
#pragma unroll
                for (int mt = 0; mt < 2; mt++){
                    MMA_BF16(acc[mt][nt], ah[mt], bh[nt]);
                    MMA_BF16(acc[mt][nt], ah[mt], bl[nt]);
                    MMA_BF16(acc[mt][nt], al[mt], bh[nt]);
                }
            }
        }
        __syncthreads();
    }

    // epilogue
    const int quad = lane >> 2, tq = lane & 3;
#pragma unroll
    for (int mt = 0; mt < 2; mt++){
        const int r0 = bm*128 + wm*32 + mt*16 + quad;
#pragma unroll
        for (int nt = 0; nt < 8; nt++){
            const int col = bn*128 + wn*64 + nt*8 + tq*2;
            float v0 = acc[mt][nt][0], v1 = acc[mt][nt][1];
            float v2 = acc[mt][nt][2], v3 = acc[mt][nt][3];
            if (EPI == 1){
                const float b0 = bias[col], b1 = bias[col+1];
                v0 += b0; v1 += b1; v2 += b0; v3 += b1;
                v0 = (v0 > 20.f) ? v0 : log1pf(__expf(v0));
                v1 = (v1 > 20.f) ? v1 : log1pf(__expf(v1));
                v2 = (v2 > 20.f) ? v2 : log1pf(__expf(v2));
                v3 = (v3 > 20.f) ? v3 : log1pf(__expf(v3));
            }
            *(float2*)(C + (size_t)r0*N + col)     = make_float2(v0, v1);
            *(float2*)(C + (size_t)(r0+8)*N + col) = make_float2(v2, v3);
        }
    }
}

// ====================== conversion kernels =================================
__global__ void __launch_bounds__(256) split_kernel(const float* __restrict__ in,
        __nv_bfloat16* __restrict__ h, __nv_bfloat16* __restrict__ l, int n)
{
    int i = blockIdx.x*256 + threadIdx.x;
    if (i < n){
        float v = in[i];
        __nv_bfloat16 hh = __float2bfloat16(v);
        h[i] = hh;
        l[i] = __float2bfloat16(v - __bfloat162float(hh));
    }
}

// W[K,N] row-major -> Th/Tl[N,K] bf16 split
__global__ void __launch_bounds__(256) transpose_split(const float* __restrict__ W,
        __nv_bfloat16* __restrict__ Th, __nv_bfloat16* __restrict__ Tl, int K, int N)
{
    __shared__ float t[32][33];
    const int tx = threadIdx.x & 31, ty = threadIdx.x >> 5;   // 32x8
    const int nb = blockIdx.x*32, kb = blockIdx.y*32;
#pragma unroll
    for (int i = 0; i < 32; i += 8)
        t[ty+i][tx] = W[(size_t)(kb+ty+i)*N + nb+tx];
    __syncthreads();
#pragma unroll
    for (int i = 0; i < 32; i += 8){
        float v = t[tx][ty+i];
        __nv_bfloat16 h = __float2bfloat16(v);
        size_t o = (size_t)(nb+ty+i)*K + kb+tx;
        Th[o] = h;
        Tl[o] = __float2bfloat16(v - __bfloat162float(h));
    }
}

// ---------------- causal depthwise conv (K=4) + SiLU + bf16 split ----------
__global__ void __launch_bounds__(256) conv_silu_kernel(const float* __restrict__ cw,
                                                        const float* __restrict__ cb)
{
    const int d  = blockIdx.x*256 + threadIdx.x;
    const int l0 = blockIdx.y * 8;
    const int b  = blockIdx.z;

    const float w0 = cw[d*4+0], w1 = cw[d*4+1], w2 = cw[d*4+2], w3 = cw[d*4+3];
    const float bb = cb[d];

    const float* xin = g_xz + (size_t)(b*SEQ)*(2*DI) + d;
    const size_t obase = (size_t)(b*SEQ + l0)*DI + d;

    float win0, win1, win2;
    {
        int l = l0 - 3; win0 = (l >= 0) ? xin[(size_t)l*(2*DI)] : 0.f;
        l = l0 - 2;     win1 = (l >= 0) ? xin[(size_t)l*(2*DI)] : 0.f;
        l = l0 - 1;     win2 = (l >= 0) ? xin[(size_t)l*(2*DI)] : 0.f;
    }
#pragma unroll
    for (int i = 0; i < 8; i++){
        float cur = xin[(size_t)(l0 + i)*(2*DI)];
        float v = w0*win0 + w1*win1 + w2*win2 + w3*cur + bb;
        float sv = v / (1.f + __expf(-v));
        size_t o = obase + (size_t)i*DI;
        g_xc[o] = sv;
        __nv_bfloat16 hh = __float2bfloat16(sv);
        g_xch[o] = hh;
        g_xcl[o] = __float2bfloat16(sv - __bfloat162float(hh));
        win0 = win1; win1 = win2; win2 = cur;
    }
}

// ---------------- small-N GEMM: bdt = xc @ W_x (N=32) ----------------------
__global__ void __launch_bounds__(256) bdt_kernel(const float* __restrict__ Wx)
{
    const int warp = (blockIdx.x*blockDim.x + threadIdx.x) >> 5;
    const int lane = threadIdx.x & 31;
    if (warp >= ROWS) return;

    const float* xr = g_xc + (size_t)warp*DI;
    float acc = 0.f;
    for (int k = 0; k < DI; k += 8){
#pragma unroll
        for (int u = 0; u < 8; u++)
            acc += xr[k+u] * Wx[(k+u)*32 + lane];
    }
    g_bdt[(size_t)warp*32 + lane] = acc;
}

// ---------------- selective scan (smem-staged, cp.async pipelined) ---------
__global__ void __launch_bounds__(128) scan_kernel(const float* __restrict__ A_log,
                                                   const float* __restrict__ Dp)
{
    __shared__ float sdt[2][16][32], sx[2][16][32], sz[2][16][32], sbc[2][16][32];
    __shared__ __nv_bfloat16 syh[16][32], syl[16][32];

    const int b = blockIdx.x, dblk = blockIdx.y, tid = threadIdx.x;
    const int c = tid >> 2, s = tid & 3, d = dblk*32 + c;

    float4 Al = *(const float4*)&A_log[(size_t)d*NS + s*4];
    const float A0 = -__expf(Al.x), A1 = -__expf(Al.y),
                A2 = -__expf(Al.z), A3 = -__expf(Al.w);
    const float Dpar = Dp[d];

    const int lr = tid >> 3, lq = tid & 7;
    const size_t base = (size_t)b*SEQ;

    float h0=0.f, h1=0.f, h2=0.f, h3=0.f;

    {
        size_t row = base + lr;
        cp16(&sdt[0][lr][lq*4], g_dt + row*DI + dblk*32 + lq*4);
        cp16(&sx [0][lr][lq*4], g_xc + row*DI + dblk*32 + lq*4);
        cp16(&sz [0][lr][lq*4], g_xz + row*(size_t)(2*DI) + DI + dblk*32 + lq*4);
        cp16(&sbc[0][lr][lq*4], g_bdt + row*32 + lq*4);
        cp_commit();
    }

    for (int tile = 0; tile < SEQ/16; tile++){
        const int buf = tile & 1;
        if (tile + 1 < SEQ/16){
            size_t row = base + (tile+1)*16 + lr;
            cp16(&sdt[buf^1][lr][lq*4], g_dt + row*DI + dblk*32 + lq*4);
            cp16(&sx [buf^1][lr][lq*4], g_xc + row*DI + dblk*32 + lq*4);
            cp16(&sz [buf^1][lr][lq*4], g_xz + row*(size_t)(2*DI) + DI + dblk*32 + lq*4);
            cp16(&sbc[buf^1][lr][lq*4], g_bdt + row*32 + lq*4);
            cp_commit();
            cp_wait<1>();
        } else {
            cp_wait<0>();
        }
        __syncthreads();

#pragma unroll 4
        for (int i = 0; i < 16; i++){
            const float dt_c = sdt[buf][i][c];
            const float x_c  = sx[buf][i][c];
            const float4 B_c = *(const float4*)&sbc[buf][i][s*4];
            const float4 C_c = *(const float4*)&sbc[buf][i][16 + s*4];
            const float dx = dt_c*x_c;
            h0 = __expf(dt_c*A0)*h0 + dx*B_c.x;
            h1 = __expf(dt_c*A1)*h1 + dx*B_c.y;
            h2 = __expf(dt_c*A2)*h2 + dx*B_c.z;
            h3 = __expf(dt_c*A3)*h3 + dx*B_c.w;
            float y = h0*C_c.x + h1*C_c.y + h2*C_c.z + h3*C_c.w;
            y += __shfl_down_sync(0xffffffffu, y, 2, 4);
            y += __shfl_down_sync(0xffffffffu, y, 1, 4);
            if (s == 0){
                const float z_c = sz[buf][i][c];
                const float v = (y + x_c*Dpar) * (z_c / (1.f + __expf(-z_c)));
                __nv_bfloat16 hh = __float2bfloat16(v);
                syh[i][c] = hh;
                syl[i][c] = __float2bfloat16(v - __bfloat162float(hh));
            }
        }
        __syncthreads();
        size_t o = (base + tile*16 + lr)*DI + dblk*32 + lq*4;
        *(uint2*)&g_yzh[o] = *(uint2*)&syh[lr][lq*4];
        *(uint2*)&g_yzl[o] = *(uint2*)&syl[lr][lq*4];
    }
}

// ===========================================================================
extern "C" void kernel_launch(void* const* d_in, const int* in_sizes, int n_in,
                              void* d_out, int out_size)
{
    const float* x      = (const float*)d_in[0];
    const float* W_in   = (const float*)d_in[1];
    const float* conv_w = (const float*)d_in[2];
    const float* conv_b = (const float*)d_in[3];
    const float* W_x    = (const float*)d_in[4];
    const float* W_dt   = (const float*)d_in[5];
    const float* b_dt   = (const float*)d_in[6];
    const float* W_out  = (const float*)d_in[7];
    const float* A_log  = (const float*)d_in[8];
    const float* D_par  = (const float*)d_in[9];
    float* out = (float*)d_out;

    float *xz, *dt;
    cudaGetSymbolAddress((void**)&xz, g_xz);
    cudaGetSymbolAddress((void**)&dt, g_dt);
    __nv_bfloat16 *xh,*xl,*xch,*xcl,*yzh,*yzl,*winh,*winl,*wdth,*wdtl,*wouth,*woutl;
    cudaGetSymbolAddress((void**)&xh,  g_xh);   cudaGetSymbolAddress((void**)&xl,  g_xl);
    cudaGetSymbolAddress((void**)&xch, g_xch);  cudaGetSymbolAddress((void**)&xcl, g_xcl);
    cudaGetSymbolAddress((void**)&yzh, g_yzh);  cudaGetSymbolAddress((void**)&yzl, g_yzl);
    cudaGetSymbolAddress((void**)&winh,g_winh); cudaGetSymbolAddress((void**)&winl,g_winl);
    cudaGetSymbolAddress((void**)&wdth,g_wdth); cudaGetSymbolAddress((void**)&wdtl,g_wdtl);
    cudaGetSymbolAddress((void**)&wouth,g_wouth); cudaGetSymbolAddress((void**)&woutl,g_woutl);

    cudaFuncSetAttribute(gemm_mma<0>, cudaFuncAttributeMaxDynamicSharedMemorySize, SMEM_GEMM);
    cudaFuncSetAttribute(gemm_mma<1>, cudaFuncAttributeMaxDynamicSharedMemorySize, SMEM_GEMM);

    // 0a) split x -> bf16 hi/lo
    split_kernel<<<(ROWS*DM + 255)/256, 256>>>(x, xh, xl, ROWS*DM);
    // 0b) transpose+split weights: W[K,N] -> [N,K]
    transpose_split<<<dim3((2*DI)/32, DM/32), 256>>>(W_in,  winh,  winl,  DM, 2*DI);
    transpose_split<<<dim3(DI/32,     DI/32), 256>>>(W_dt,  wdth,  wdtl,  DI, DI);
    transpose_split<<<dim3(DM/32,     DI/32), 256>>>(W_out, wouth, woutl, DI, DM);

    // 1) xz = x @ W_in                     (8192 x 4096 x 1024)
    gemm_mma<0><<<dim3((2*DI)/128, ROWS/128), 256, SMEM_GEMM>>>(
        xh, xl, winh, winl, xz, ROWS, 2*DI, DM, nullptr);

    // 2) xc = silu(causal_dwconv(x_inner)) (+ bf16 split)
    conv_silu_kernel<<<dim3(DI/256, SEQ/8, BATCH), 256>>>(conv_w, conv_b);

    // 3) bdt = xc @ W_x                    (N = 32, fp32 CUDA cores)
    bdt_kernel<<<ROWS/8, 256>>>(W_x);

    // 4) dt = softplus(xc @ W_dt + b_dt)   (8192 x 2048 x 2048)
    gemm_mma<1><<<dim3(DI/128, ROWS/128), 256, SMEM_GEMM>>>(
        xch, xcl, wdth, wdtl, dt, ROWS, DI, DI, b_dt);

    // 5) selective scan + skip + gating -> yz (bf16 hi/lo)
    scan_kernel<<<dim3(BATCH, DI/32), 128>>>(A_log, D_par);

    // 6) out = yz @ W_out                  (8192 x 1024 x 2048)
    gemm_mma<0><<<dim3(DM/128, ROWS/128), 256, SMEM_GEMM>>>(
        yzh, yzl, wouth, woutl, out, ROWS, DM, DI, nullptr);
}

// round 4
// speedup vs baseline: 2.8886x; 1.0258x over previous
#include <cuda_runtime.h>
#include <cuda_bf16.h>
#include <stdint.h>
#include <math.h>

#define BATCH 4
#define SEQ 2048
#define DM 1024
#define DI 2048
#define NS 16
#define ROWS (BATCH*SEQ)   /* 8192 */

// ---------------- scratch (static device arrays; no cudaMalloc) ------------
__device__ float g_xz [(size_t)ROWS*(2*DI)];   // in_proj output [x_inner | z]
__device__ float g_xc [(size_t)ROWS*DI];       // conv+silu output (fp32)
__device__ float g_bdt[(size_t)ROWS*(2*NS)];   // [B | C]
__device__ float g_dt [(size_t)ROWS*DI];       // softplus(xc@W_dt + b)

// bf16 split activations
__device__ __nv_bfloat16 g_xh  [(size_t)ROWS*DM],  g_xl  [(size_t)ROWS*DM];
__device__ __nv_bfloat16 g_xch [(size_t)ROWS*DI],  g_xcl [(size_t)ROWS*DI];
__device__ __nv_bfloat16 g_yzh [(size_t)ROWS*DI],  g_yzl [(size_t)ROWS*DI];
// bf16 split transposed weights [N, K]
__device__ __nv_bfloat16 g_winh [(size_t)(2*DI)*DM], g_winl [(size_t)(2*DI)*DM];
__device__ __nv_bfloat16 g_wdth [(size_t)DI*DI],     g_wdtl [(size_t)DI*DI];
__device__ __nv_bfloat16 g_wouth[(size_t)DM*DI],     g_woutl[(size_t)DM*DI];

// ====================== PTX helpers =======================================
__device__ __forceinline__ uint32_t smem_u32(const void* p){
    return (uint32_t)__cvta_generic_to_shared(p);
}
__device__ __forceinline__ void cp16(void* s, const void* g){
    uint32_t sa = smem_u32(s);
    asm volatile("cp.async.cg.shared.global [%0], [%1], 16;" :: "r"(sa), "l"(g) : "memory");
}
__device__ __forceinline__ void cp16s(uint32_t sa, const void* g){
    asm volatile("cp.async.cg.shared.global [%0], [%1], 16;" :: "r"(sa), "l"(g) : "memory");
}
__device__ __forceinline__ void cp_commit(){ asm volatile("cp.async.commit_group;" ::: "memory"); }
template<int N> __device__ __forceinline__ void cp_wait(){ asm volatile("cp.async.wait_group %0;" :: "n"(N) : "memory"); }

#define SWZ(o)   ((o) ^ (((o)>>3)&0x70))   /* 128B-row swizzle */
#define SWZ64(o) ((o) ^ (((o)>>3)&0x30))   /* 64B-row swizzle  */

#define LDSM4(r0,r1,r2,r3,addr) \
    asm volatile("ldmatrix.sync.aligned.m8n8.x4.shared.b16 {%0,%1,%2,%3}, [%4];" \
        : "=r"(r0),"=r"(r1),"=r"(r2),"=r"(r3) : "r"(addr))

#define MMA_BF16(c, a, b) \
    asm volatile("mma.sync.aligned.m16n8k16.row.col.f32.bf16.bf16.f32 " \
        "{%0,%1,%2,%3},{%4,%5,%6,%7},{%8,%9},{%0,%1,%2,%3};" \
        : "+f"((c)[0]),"+f"((c)[1]),"+f"((c)[2]),"+f"((c)[3]) \
        : "r"((a)[0]),"r"((a)[1]),"r"((a)[2]),"r"((a)[3]),"r"((b)[0]),"r"((b)[1]))

// ====================== HMMA bf16-split GEMM ===============================
// C[M,N] = (Ah+Al)[M,K] @ (Bh+Bl)[N,K]^T   (B row-major [N,K])
// acc = Ah*Bh + Ah*Bl + Al*Bh.   EPI==1: softplus(v + bias[n]).
// CTA tile 128x128, BK=32, 3-stage cp.async ring, 2 CTAs/SM.
static const int T_AH = 0, T_AL = 8192, T_BH = 16384, T_BL = 24576;
static const int STG  = 32768;            // one stage: 4 tiles x 8KB (128 rows x 64B)
static const int NSTG = 3;
static const int SMEM_GEMM = NSTG*STG;    // 98304

template<int EPI>
__global__ void __launch_bounds__(256,2)
gemm_mma(const __nv_bfloat16* __restrict__ Ah, const __nv_bfloat16* __restrict__ Al,
         const __nv_bfloat16* __restrict__ Bh, const __nv_bfloat16* __restrict__ Bl,
         float* __restrict__ C, int M, int N, int K, const float* __restrict__ bias)
{
    extern __shared__ char smem[];
    const uint32_t sb = smem_u32(smem);
    const int tid = threadIdx.x, wid = tid>>5, lane = tid&31;
    const int bm = blockIdx.y, bn = blockIdx.x;
    const int wm = wid & 3, wn = wid >> 2;     // warp tile: rows wm*32, cols wn*64

    const __nv_bfloat16* gsrc[4] = {
        Ah + (size_t)(bm*128)*K, Al + (size_t)(bm*128)*K,
        Bh + (size_t)(bn*128)*K, Bl + (size_t)(bn*128)*K };

    const int nk = K/32;

    // loader: per tile 512 chunks of 16B; thread does 2 (tid, tid+256)
    const int lr0 = tid >> 2, lr1 = (tid+256) >> 2;
    const int lc0 = tid & 3,  lc1 = (tid+256) & 3;

    auto load_stage = [&](int stage, int c0){
        const uint32_t dst = sb + stage*STG;
        const size_t coff = (size_t)c0*32;
#pragma unroll
        for (int t = 0; t < 4; t++){
            const __nv_bfloat16* g = gsrc[t] + coff;
            const uint32_t st = dst + t*8192;
            cp16s(st + SWZ64((lr0<<6) + (lc0<<4)), g + (size_t)lr0*K + lc0*8);
            cp16s(st + SWZ64((lr1<<6) + (lc1<<4)), g + (size_t)lr1*K + lc1*8);
        }
        cp_commit();
    };

    float acc[2][8][4];
#pragma unroll
    for (int mt=0; mt<2; mt++)
#pragma unroll
        for (int nt=0; nt<8; nt++)
#pragma unroll
            for (int j=0; j<4; j++) acc[mt][nt][j] = 0.f;

    // lane-derived ldmatrix row/col pieces
    const int lrr = lane & 7;
    const int a_row0 = wm*32 + ((lane>>3)&1)*8 + lrr;     // + mt*16
    const int a_coff = (lane>>4)*16;                      // k-half byte offset
    const int b_row0 = wn*64 + (lane>>4)*8 + lrr;         // + np*16
    const int b_coff = ((lane>>3)&1)*16;

    load_stage(0, 0);
    load_stage(1, 1);

    for (int k0 = 0; k0 < nk; k0++){
        if (k0+2 < nk){ load_stage((k0+2)%NSTG, k0+2); cp_wait<2>(); }
        else if (k0+1 < nk){ cp_wait<1>(); }
        else { cp_wait<0>(); }
        __syncthreads();

        const uint32_t st = sb + (k0%NSTG)*STG;
        const uint32_t aH = st + T_AH, aL = st + T_AL;
        const uint32_t bH = st + T_BH, bL = st + T_BL;

#pragma unroll
        for (int kk = 0; kk < 2; kk++){
            uint32_t ah[2][4], al[2][4];
#pragma unroll
            for (int mt = 0; mt < 2; mt++){
                uint32_t off = SWZ64(((a_row0 + mt*16)<<6) + kk*32 + a_coff);
                LDSM4(ah[mt][0],ah[mt][1],ah[mt][2],ah[mt][3], aH + off);
                LDSM4(al[mt][0],al[mt][1],al[mt][2],al[mt][3], aL + off);
            }
            // two half-batches of B to cap register liveness
#pragma unroll
            for (int half = 0; half < 2; half++){
                uint32_t bh[4][2], bl[4][2];
#pragma unroll
                for (int np = 0; np < 2; np++){
                    uint32_t off = SWZ64(((b_row0 + (half*2+np)*16)<<6) + kk*32 + b_coff);
                    LDSM4(bh[np*2][0],bh[np*2][1],bh[np*2+1][0],bh[np*2+1][1], bH + off);
                    LDSM4(bl[np*2][0],bl[np*2][1],bl[np*2+1][0],bl[np*2+1][1], bL + off);
                }
#pragma unroll
                for (int nt = 0; nt < 4; nt++){
#pragma unroll
                    for (int mt = 0; mt < 2; mt++){
                        float* a4 = acc[mt][half*4+nt];
                        MMA_BF16(a4, ah[mt], bh[nt]);
                        MMA_BF16(a4, ah[mt], bl[nt]);
                        MMA_BF16(a4, al[mt], bh[nt]);
                    }
                }
            }
        }
        __syncthreads();
    }

    // epilogue
    const int quad = lane >> 2, tq = lane & 3;
#pragma unroll
    for (int mt = 0; mt < 2; mt++){
        const int r0 = bm*128 + wm*32 + mt*16 + quad;
#pragma unroll
        for (int nt = 0; nt < 8; nt++){
            const int col = bn*128 + wn*64 + nt*8 + tq*2;
            float v0 = acc[mt][nt][0], v1 = acc[mt][nt][1];
            float v2 = acc[mt][nt][2], v3 = acc[mt][nt][3];
            if (EPI == 1){
                const float b0 = bias[col], b1 = bias[col+1];
                v0 += b0; v1 += b1; v2 += b0; v3 += b1;
                v0 = (v0 > 20.f) ? v0 : log1pf(__expf(v0));
                v1 = (v1 > 20.f) ? v1 : log1pf(__expf(v1));
                v2 = (v2 > 20.f) ? v2 : log1pf(__expf(v2));
                v3 = (v3 > 20.f) ? v3 : log1pf(__expf(v3));
            }
            *(float2*)(C + (size_t)r0*N + col)     = make_float2(v0, v1);
            *(float2*)(C + (size_t)(r0+8)*N + col) = make_float2(v2, v3);
        }
    }
}

// ====================== conversion kernels =================================
__global__ void __launch_bounds__(256) split_kernel(const float* __restrict__ in,
        __nv_bfloat16* __restrict__ h, __nv_bfloat16* __restrict__ l, int n)
{
    int i = blockIdx.x*256 + threadIdx.x;
    if (i < n){
        float v = in[i];
        __nv_bfloat16 hh = __float2bfloat16(v);
        h[i] = hh;
        l[i] = __float2bfloat16(v - __bfloat162float(hh));
    }
}

// W[K,N] row-major -> Th/Tl[N,K] bf16 split
__global__ void __launch_bounds__(256) transpose_split(const float* __restrict__ W,
        __nv_bfloat16* __restrict__ Th, __nv_bfloat16* __restrict__ Tl, int K, int N)
{
    __shared__ float t[32][33];
    const int tx = threadIdx.x & 31, ty = threadIdx.x >> 5;   // 32x8
    const int nb = blockIdx.x*32, kb = blockIdx.y*32;
#pragma unroll
    for (int i = 0; i < 32; i += 8)
        t[ty+i][tx] = W[(size_t)(kb+ty+i)*N + nb+tx];
    __syncthreads();
#pragma unroll
    for (int i = 0; i < 32; i += 8){
        float v = t[tx][ty+i];
        __nv_bfloat16 h = __float2bfloat16(v);
        size_t o = (size_t)(nb+ty+i)*K + kb+tx;
        Th[o] = h;
        Tl[o] = __float2bfloat16(v - __bfloat162float(h));
    }
}

// ---------------- causal depthwise conv (K=4) + SiLU + bf16 split ----------
__global__ void __launch_bounds__(256) conv_silu_kernel(const float* __restrict__ cw,
                                                        const float* __restrict__ cb)
{
    const int d  = blockIdx.x*256 + threadIdx.x;
    const int l0 = blockIdx.y * 8;
    const int b  = blockIdx.z;

    const float w0 = cw[d*4+0], w1 = cw[d*4+1], w2 = cw[d*4+2], w3 = cw[d*4+3];
    const float bb = cb[d];

    const float* xin = g_xz + (size_t)(b*SEQ)*(2*DI) + d;
    const size_t obase = (size_t)(b*SEQ + l0)*DI + d;

    float win0, win1, win2;
    {
        int l = l0 - 3; win0 = (l >= 0) ? xin[(size_t)l*(2*DI)] : 0.f;
        l = l0 - 2;     win1 = (l >= 0) ? xin[(size_t)l*(2*DI)] : 0.f;
        l = l0 - 1;     win2 = (l >= 0) ? xin[(size_t)l*(2*DI)] : 0.f;
    }
#pragma unroll
    for (int i = 0; i < 8; i++){
        float cur = xin[(size_t)(l0 + i)*(2*DI)];
        float v = w0*win0 + w1*win1 + w2*win2 + w3*cur + bb;
        float sv = v / (1.f + __expf(-v));
        size_t o = obase + (size_t)i*DI;
        g_xc[o] = sv;
        __nv_bfloat16 hh = __float2bfloat16(sv);
        g_xch[o] = hh;
        g_xcl[o] = __float2bfloat16(sv - __bfloat162float(hh));
        win0 = win1; win1 = win2; win2 = cur;
    }
}

// ---------------- small-N GEMM: bdt = xc @ W_x (N=32) ----------------------
__global__ void __launch_bounds__(256) bdt_kernel(const float* __restrict__ Wx)
{
    const int warp = (blockIdx.x*blockDim.x + threadIdx.x) >> 5;
    const int lane = threadIdx.x & 31;
    if (warp >= ROWS) return;

    const float* xr = g_xc + (size_t)warp*DI;
    float acc = 0.f;
    for (int k = 0; k < DI; k += 8){
#pragma unroll
        for (int u = 0; u < 8; u++)
            acc += xr[k+u] * Wx[(k+u)*32 + lane];
    }
    g_bdt[(size_t)warp*32 + lane] = acc;
}

// ---------------- selective scan (smem-staged, cp.async pipelined) ---------
__global__ void __launch_bounds__(128) scan_kernel(const float* __restrict__ A_log,
                                                   const float* __restrict__ Dp)
{
    __shared__ float sdt[2][16][32], sx[2][16][32], sz[2][16][32], sbc[2][16][32];
    __shared__ __nv_bfloat16 syh[16][32], syl[16][32];

    const int b = blockIdx.x, dblk = blockIdx.y, tid = threadIdx.x;
    const int c = tid >> 2, s = tid & 3, d = dblk*32 + c;

    float4 Al = *(const float4*)&A_log[(size_t)d*NS + s*4];
    const float A0 = -__expf(Al.x), A1 = -__expf(Al.y),
                A2 = -__expf(Al.z), A3 = -__expf(Al.w);
    const float Dpar = Dp[d];

    const int lr = tid >> 3, lq = tid & 7;
    const size_t base = (size_t)b*SEQ;

    float h0=0.f, h1=0.f, h2=0.f, h3=0.f;

    {
        size_t row = base + lr;
        cp16(&sdt[0][lr][lq*4], g_dt + row*DI + dblk*32 + lq*4);
        cp16(&sx [0][lr][lq*4], g_xc + row*DI + dblk*32 + lq*4);
        cp16(&sz [0][lr][lq*4], g_xz + row*(size_t)(2*DI) + DI + dblk*32 + lq*4);
        cp16(&sbc[0][lr][lq*4], g_bdt + row*32 + lq*4);
        cp_commit();
    }

    for (int tile = 0; tile < SEQ/16; tile++){
        const int buf = tile & 1;
        if (tile + 1 < SEQ/16){
            size_t row = base + (tile+1)*16 + lr;
            cp16(&sdt[buf^1][lr][lq*4], g_dt + row*DI + dblk*32 + lq*4);
            cp16(&sx [buf^1][lr][lq*4], g_xc + row*DI + dblk*32 + lq*4);
            cp16(&sz [buf^1][lr][lq*4], g_xz + row*(size_t)(2*DI) + DI + dblk*32 + lq*4);
            cp16(&sbc[buf^1][lr][lq*4], g_bdt + row*32 + lq*4);
            cp_commit();
            cp_wait<1>();
        } else {
            cp_wait<0>();
        }
        __syncthreads();

#pragma unroll 4
        for (int i = 0; i < 16; i++){
            const float dt_c = sdt[buf][i][c];
            const float x_c  = sx[buf][i][c];
            const float4 B_c = *(const float4*)&sbc[buf][i][s*4];
            const float4 C_c = *(const float4*)&sbc[buf][i][16 + s*4];
            const float dx = dt_c*x_c;
            h0 = __expf(dt_c*A0)*h0 + dx*B_c.x;
            h1 = __expf(dt_c*A1)*h1 + dx*B_c.y;
            h2 = __expf(dt_c*A2)*h2 + dx*B_c.z;
            h3 = __expf(dt_c*A3)*h3 + dx*B_c.w;
            float y = h0*C_c.x + h1*C_c.y + h2*C_c.z + h3*C_c.w;
            y += __shfl_down_sync(0xffffffffu, y, 2, 4);
            y += __shfl_down_sync(0xffffffffu, y, 1, 4);
            if (s == 0){
                const float z_c = sz[buf][i][c];
                const float v = (y + x_c*Dpar) * (z_c / (1.f + __expf(-z_c)));
                __nv_bfloat16 hh = __float2bfloat16(v);
                syh[i][c] = hh;
                syl[i][c] = __float2bfloat16(v - __bfloat162float(hh));
            }
        }
        __syncthreads();
        size_t o = (base + tile*16 + lr)*DI + dblk*32 + lq*4;
        *(uint2*)&g_yzh[o] = *(uint2*)&syh[lr][lq*4];
        *(uint2*)&g_yzl[o] = *(uint2*)&syl[lr][lq*4];
    }
}

// ===========================================================================
extern "C" void kernel_launch(void* const* d_in, const int* in_sizes, int n_in,
                              void* d_out, int out_size)
{
    const float* x      = (const float*)d_in[0];
    const float* W_in   = (const float*)d_in[1];
    const float* conv_w = (const float*)d_in[2];
    const float* conv_b = (const float*)d_in[3];
    const float* W_x    = (const float*)d_in[4];
    const float* W_dt   = (const float*)d_in[5];
    const float* b_dt   = (const float*)d_in[6];
    const float* W_out  = (const float*)d_in[7];
    const float* A_log  = (const float*)d_in[8];
    const float* D_par  = (const float*)d_in[9];
    float* out = (float*)d_out;

    float *xz, *dt;
    cudaGetSymbolAddress((void**)&xz, g_xz);
    cudaGetSymbolAddress((void**)&dt, g_dt);
    __nv_bfloat16 *xh,*xl,*xch,*xcl,*yzh,*yzl,*winh,*winl,*wdth,*wdtl,*wouth,*woutl;
    cudaGetSymbolAddress((void**)&xh,  g_xh);   cudaGetSymbolAddress((void**)&xl,  g_xl);
    cudaGetSymbolAddress((void**)&xch, g_xch);  cudaGetSymbolAddress((void**)&xcl, g_xcl);
    cudaGetSymbolAddress((void**)&yzh, g_yzh);  cudaGetSymbolAddress((void**)&yzl, g_yzl);
    cudaGetSymbolAddress((void**)&winh,g_winh); cudaGetSymbolAddress((void**)&winl,g_winl);
    cudaGetSymbolAddress((void**)&wdth,g_wdth); cudaGetSymbolAddress((void**)&wdtl,g_wdtl);
    cudaGetSymbolAddress((void**)&wouth,g_wouth); cudaGetSymbolAddress((void**)&woutl,g_woutl);

    cudaFuncSetAttribute(gemm_mma<0>, cudaFuncAttributeMaxDynamicSharedMemorySize, SMEM_GEMM);
    cudaFuncSetAttribute(gemm_mma<1>, cudaFuncAttributeMaxDynamicSharedMemorySize, SMEM_GEMM);

    // 0a) split x -> bf16 hi/lo
    split_kernel<<<(ROWS*DM + 255)/256, 256>>>(x, xh, xl, ROWS*DM);
    // 0b) transpose+split weights: W[K,N] -> [N,K]
    transpose_split<<<dim3((2*DI)/32, DM/32), 256>>>(W_in,  winh,  winl,  DM, 2*DI);
    transpose_split<<<dim3(DI/32,     DI/32), 256>>>(W_dt,  wdth,  wdtl,  DI, DI);
    transpose_split<<<dim3(DM/32,     DI/32), 256>>>(W_out, wouth, woutl, DI, DM);

    // 1) xz = x @ W_in                     (8192 x 4096 x 1024)
    gemm_mma<0><<<dim3((2*DI)/128, ROWS/128), 256, SMEM_GEMM>>>(
        xh, xl, winh, winl, xz, ROWS, 2*DI, DM, nullptr);

    // 2) xc = silu(causal_dwconv(x_inner)) (+ bf16 split)
    conv_silu_kernel<<<dim3(DI/256, SEQ/8, BATCH), 256>>>(conv_w, conv_b);

    // 3) bdt = xc @ W_x                    (N = 32, fp32 CUDA cores)
    bdt_kernel<<<ROWS/8, 256>>>(W_x);

    // 4) dt = softplus(xc @ W_dt + b_dt)   (8192 x 2048 x 2048)
    gemm_mma<1><<<dim3(DI/128, ROWS/128), 256, SMEM_GEMM>>>(
        xch, xcl, wdth, wdtl, dt, ROWS, DI, DI, b_dt);

    // 5) selective scan + skip + gating -> yz (bf16 hi/lo)
    scan_kernel<<<dim3(BATCH, DI/32), 128>>>(A_log, D_par);

    // 6) out = yz @ W_out                  (8192 x 1024 x 2048)
    gemm_mma<0><<<dim3(DM/128, ROWS/128), 256, SMEM_GEMM>>>(
        yzh, yzl, wouth, woutl, out, ROWS, DM, DI, nullptr);
}

// round 5
// speedup vs baseline: 2.9048x; 1.0056x over previous
#include <cuda_runtime.h>
#include <cuda_fp16.h>
#include <stdint.h>
#include <math.h>

#define BATCH 4
#define SEQ 2048
#define DM 1024
#define DI 2048
#define NS 16
#define ROWS (BATCH*SEQ)   /* 8192 */

// ---------------- scratch (static device arrays; no cudaMalloc) ------------
__device__ float g_xz [(size_t)ROWS*(2*DI)];   // in_proj output [x_inner | z]
__device__ float g_xc [(size_t)ROWS*DI];       // conv+silu output (fp32)
__device__ float g_bdt[(size_t)ROWS*(2*NS)];   // [B | C]
__device__ float g_dt [(size_t)ROWS*DI];       // softplus(xc@W_dt + b)

// fp16 split activations (hi + lo)
__device__ __half g_xh  [(size_t)ROWS*DM],  g_xl  [(size_t)ROWS*DM];
__device__ __half g_xch [(size_t)ROWS*DI],  g_xcl [(size_t)ROWS*DI];
__device__ __half g_yzh [(size_t)ROWS*DI],  g_yzl [(size_t)ROWS*DI];
// fp16 transposed weights [N, K] (single precision copy)
__device__ __half g_win [(size_t)(2*DI)*DM];
__device__ __half g_wdt [(size_t)DI*DI];
__device__ __half g_wout[(size_t)DM*DI];

// ====================== PTX helpers =======================================
__device__ __forceinline__ uint32_t smem_u32(const void* p){
    return (uint32_t)__cvta_generic_to_shared(p);
}
__device__ __forceinline__ void cp16(void* s, const void* g){
    uint32_t sa = smem_u32(s);
    asm volatile("cp.async.cg.shared.global [%0], [%1], 16;" :: "r"(sa), "l"(g) : "memory");
}
__device__ __forceinline__ void cp16s(uint32_t sa, const void* g){
    asm volatile("cp.async.cg.shared.global [%0], [%1], 16;" :: "r"(sa), "l"(g) : "memory");
}
__device__ __forceinline__ void cp_commit(){ asm volatile("cp.async.commit_group;" ::: "memory"); }
template<int N> __device__ __forceinline__ void cp_wait(){ asm volatile("cp.async.wait_group %0;" :: "n"(N) : "memory"); }

#define SWZ64(o) ((o) ^ (((o)>>3)&0x30))   /* 64B-row swizzle */

#define LDSM4(r0,r1,r2,r3,addr) \
    asm volatile("ldmatrix.sync.aligned.m8n8.x4.shared.b16 {%0,%1,%2,%3}, [%4];" \
        : "=r"(r0),"=r"(r1),"=r"(r2),"=r"(r3) : "r"(addr))

#define MMA_F16(c, a, b) \
    asm volatile("mma.sync.aligned.m16n8k16.row.col.f32.f16.f16.f32 " \
        "{%0,%1,%2,%3},{%4,%5,%6,%7},{%8,%9},{%0,%1,%2,%3};" \
        : "+f"((c)[0]),"+f"((c)[1]),"+f"((c)[2]),"+f"((c)[3]) \
        : "r"((a)[0]),"r"((a)[1]),"r"((a)[2]),"r"((a)[3]),"r"((b)[0]),"r"((b)[1]))

__device__ __forceinline__ void split_h(float v, __half& hi, __half& lo){
    hi = __float2half_rn(v);
    lo = __float2half_rn(v - __half2float(hi));
}

// ====================== HMMA fp16 2-product GEMM ===========================
// C[M,N] = (Ah+Al)[M,K] @ Bh[N,K]^T     (B row-major [N,K], single fp16)
// acc = Ah*Bh + Al*Bh  (fp32 accumulate).  EPI==1: softplus(v + bias[n]).
// CTA tile 128x128, BK=32, 4-stage cp.async ring, 2 CTAs/SM.
static const int T_AH = 0, T_AL = 8192, T_BH = 16384;
static const int STG  = 24576;            // one stage: 3 tiles x 8KB (128 rows x 64B)
static const int NSTG = 4;
static const int SMEM_GEMM = NSTG*STG;    // 98304

template<int EPI>
__global__ void __launch_bounds__(256,2)
gemm_mma(const __half* __restrict__ Ah, const __half* __restrict__ Al,
         const __half* __restrict__ Bh,
         float* __restrict__ C, int M, int N, int K, const float* __restrict__ bias)
{
    extern __shared__ char smem[];
    const uint32_t sb = smem_u32(smem);
    const int tid = threadIdx.x, wid = tid>>5, lane = tid&31;
    const int bm = blockIdx.y, bn = blockIdx.x;
    const int wm = wid & 3, wn = wid >> 2;     // warp tile: rows wm*32, cols wn*64

    const __half* gsrc[3] = {
        Ah + (size_t)(bm*128)*K, Al + (size_t)(bm*128)*K,
        Bh + (size_t)(bn*128)*K };

    const int nk = K/32;

    // loader: per tile 512 chunks of 16B; thread does 2 (tid, tid+256)
    const int lr0 = tid >> 2, lr1 = (tid+256) >> 2;
    const int lc0 = tid & 3,  lc1 = (tid+256) & 3;

    auto load_stage = [&](int stage, int c0){
        const uint32_t dst = sb + stage*STG;
        const size_t coff = (size_t)c0*32;
#pragma unroll
        for (int t = 0; t < 3; t++){
            const __half* g = gsrc[t] + coff;
            const uint32_t st = dst + t*8192;
            cp16s(st + SWZ64((lr0<<6) + (lc0<<4)), g + (size_t)lr0*K + lc0*8);
            cp16s(st + SWZ64((lr1<<6) + (lc1<<4)), g + (size_t)lr1*K + lc1*8);
        }
        cp_commit();
    };

    float acc[2][8][4];
#pragma unroll
    for (int mt=0; mt<2; mt++)
#pragma unroll
        for (int nt=0; nt<8; nt++)
#pragma unroll
            for (int j=0; j<4; j++) acc[mt][nt][j] = 0.f;

    // lane-derived ldmatrix row/col pieces
    const int lrr = lane & 7;
    const int a_row0 = wm*32 + ((lane>>3)&1)*8 + lrr;     // + mt*16
    const int a_coff = (lane>>4)*16;                      // k-half byte offset
    const int b_row0 = wn*64 + (lane>>4)*8 + lrr;         // + np*16
    const int b_coff = ((lane>>3)&1)*16;

    load_stage(0, 0);
    load_stage(1, 1);
    load_stage(2, 2);

    for (int k0 = 0; k0 < nk; k0++){
        if (k0+3 < nk){ load_stage((k0+3)%NSTG, k0+3); cp_wait<3>(); }
        else if (k0+2 < nk){ cp_wait<2>(); }
        else if (k0+1 < nk){ cp_wait<1>(); }
        else { cp_wait<0>(); }
        __syncthreads();

        const uint32_t st = sb + (k0%NSTG)*STG;
        const uint32_t aH = st + T_AH, aL = st + T_AL, bH = st + T_BH;

#pragma unroll
        for (int kk = 0; kk < 2; kk++){
            uint32_t ah[2][4], al[2][4], bh[8][2];
#pragma unroll
            for (int mt = 0; mt < 2; mt++){
                uint32_t off = SWZ64(((a_row0 + mt*16)<<6) + kk*32 + a_coff);
                LDSM4(ah[mt][0],ah[mt][1],ah[mt][2],ah[mt][3], aH + off);
                LDSM4(al[mt][0],al[mt][1],al[mt][2],al[mt][3], aL + off);
            }
#pragma unroll
            for (int np = 0; np < 4; np++){
                uint32_t off = SWZ64(((b_row0 + np*16)<<6) + kk*32 + b_coff);
                LDSM4(bh[np*2][0],bh[np*2][1],bh[np*2+1][0],bh[np*2+1][1], bH + off);
            }
#pragma unroll
            for (int nt = 0; nt < 8; nt++){
#pragma unroll
                for (int mt = 0; mt < 2; mt++){
                    float* a4 = acc[mt][nt];
                    MMA_F16(a4, ah[mt], bh[nt]);
                    MMA_F16(a4, al[mt], bh[nt]);
                }
            }
        }
        __syncthreads();
    }

    // epilogue
    const int quad = lane >> 2, tq = lane & 3;
#pragma unroll
    for (int mt = 0; mt < 2; mt++){
        const int r0 = bm*128 + wm*32 + mt*16 + quad;
#pragma unroll
        for (int nt = 0; nt < 8; nt++){
            const int col = bn*128 + wn*64 + nt*8 + tq*2;
            float v0 = acc[mt][nt][0], v1 = acc[mt][nt][1];
            float v2 = acc[mt][nt][2], v3 = acc[mt][nt][3];
            if (EPI == 1){
                const float b0 = bias[col], b1 = bias[col+1];
                v0 += b0; v1 += b1; v2 += b0; v3 += b1;
                v0 = (v0 > 20.f) ? v0 : log1pf(__expf(v0));
                v1 = (v1 > 20.f) ? v1 : log1pf(__expf(v1));
                v2 = (v2 > 20.f) ? v2 : log1pf(__expf(v2));
                v3 = (v3 > 20.f) ? v3 : log1pf(__expf(v3));
            }
            *(float2*)(C + (size_t)r0*N + col)     = make_float2(v0, v1);
            *(float2*)(C + (size_t)(r0+8)*N + col) = make_float2(v2, v3);
        }
    }
}

// ====================== conversion kernels =================================
__global__ void __launch_bounds__(256) split_kernel(const float* __restrict__ in,
        __half* __restrict__ h, __half* __restrict__ l, int n)
{
    int i = blockIdx.x*256 + threadIdx.x;
    if (i < n){
        __half hh, ll;
        split_h(in[i], hh, ll);
        h[i] = hh; l[i] = ll;
    }
}

// W[K,N] row-major -> T[N,K] fp16
__global__ void __launch_bounds__(256) transpose_half(const float* __restrict__ W,
        __half* __restrict__ T, int K, int N)
{
    __shared__ float t[32][33];
    const int tx = threadIdx.x & 31, ty = threadIdx.x >> 5;   // 32x8
    const int nb = blockIdx.x*32, kb = blockIdx.y*32;
#pragma unroll
    for (int i = 0; i < 32; i += 8)
        t[ty+i][tx] = W[(size_t)(kb+ty+i)*N + nb+tx];
    __syncthreads();
#pragma unroll
    for (int i = 0; i < 32; i += 8)
        T[(size_t)(nb+ty+i)*K + kb+tx] = __float2half_rn(t[tx][ty+i]);
}

// ---------------- causal depthwise conv (K=4) + SiLU + fp16 split ----------
__global__ void __launch_bounds__(256) conv_silu_kernel(const float* __restrict__ cw,
                                                        const float* __restrict__ cb)
{
    const int d  = blockIdx.x*256 + threadIdx.x;
    const int l0 = blockIdx.y * 8;
    const int b  = blockIdx.z;

    const float w0 = cw[d*4+0], w1 = cw[d*4+1], w2 = cw[d*4+2], w3 = cw[d*4+3];
    const float bb = cb[d];

    const float* xin = g_xz + (size_t)(b*SEQ)*(2*DI) + d;
    const size_t obase = (size_t)(b*SEQ + l0)*DI + d;

    float win0, win1, win2;
    {
        int l = l0 - 3; win0 = (l >= 0) ? xin[(size_t)l*(2*DI)] : 0.f;
        l = l0 - 2;     win1 = (l >= 0) ? xin[(size_t)l*(2*DI)] : 0.f;
        l = l0 - 1;     win2 = (l >= 0) ? xin[(size_t)l*(2*DI)] : 0.f;
    }
#pragma unroll
    for (int i = 0; i < 8; i++){
        float cur = xin[(size_t)(l0 + i)*(2*DI)];
        float v = w0*win0 + w1*win1 + w2*win2 + w3*cur + bb;
        float sv = v / (1.f + __expf(-v));
        size_t o = obase + (size_t)i*DI;
        g_xc[o] = sv;
        __half hh, ll;
        split_h(sv, hh, ll);
        g_xch[o] = hh;
        g_xcl[o] = ll;
        win0 = win1; win1 = win2; win2 = cur;
    }
}

// ---------------- small-N GEMM: bdt = xc @ W_x (N=32) ----------------------
// one warp per 8 rows: lane = output column, W_x row loads reused 8x.
__global__ void __launch_bounds__(256) bdt_kernel(const float* __restrict__ Wx)
{
    const int warp = (blockIdx.x*blockDim.x + threadIdx.x) >> 5;  // 0..1023
    const int lane = threadIdx.x & 31;
    const int r0 = warp*8;
    if (r0 >= ROWS) return;

    const float* xr = g_xc + (size_t)r0*DI;
    float acc[8] = {0,0,0,0,0,0,0,0};
    for (int k = 0; k < DI; k += 4){
#pragma unroll
        for (int u = 0; u < 4; u++){
            const float w = Wx[(k+u)*32 + lane];
#pragma unroll
            for (int r = 0; r < 8; r++)
                acc[r] += xr[(size_t)r*DI + k+u] * w;
        }
    }
#pragma unroll
    for (int r = 0; r < 8; r++)
        g_bdt[(size_t)(r0+r)*32 + lane] = acc[r];
}

// ---------------- selective scan (smem-staged, cp.async pipelined) ---------
__global__ void __launch_bounds__(128) scan_kernel(const float* __restrict__ A_log,
                                                   const float* __restrict__ Dp)
{
    __shared__ float sdt[2][16][32], sx[2][16][32], sz[2][16][32], sbc[2][16][32];
    __shared__ __half syh[16][32], syl[16][32];

    const int b = blockIdx.x, dblk = blockIdx.y, tid = threadIdx.x;
    const int c = tid >> 2, s = tid & 3, d = dblk*32 + c;

    float4 Al = *(const float4*)&A_log[(size_t)d*NS + s*4];
    const float A0 = -__expf(Al.x), A1 = -__expf(Al.y),
                A2 = -__expf(Al.z), A3 = -__expf(Al.w);
    const float Dpar = Dp[d];

    const int lr = tid >> 3, lq = tid & 7;
    const size_t base = (size_t)b*SEQ;

    float h0=0.f, h1=0.f, h2=0.f, h3=0.f;

    {
        size_t row = base + lr;
        cp16(&sdt[0][lr][lq*4], g_dt + row*DI + dblk*32 + lq*4);
        cp16(&sx [0][lr][lq*4], g_xc + row*DI + dblk*32 + lq*4);
        cp16(&sz [0][lr][lq*4], g_xz + row*(size_t)(2*DI) + DI + dblk*32 + lq*4);
        cp16(&sbc[0][lr][lq*4], g_bdt + row*32 + lq*4);
        cp_commit();
    }

    for (int tile = 0; tile < SEQ/16; tile++){
        const int buf = tile & 1;
        if (tile + 1 < SEQ/16){
            size_t row = base + (tile+1)*16 + lr;
            cp16(&sdt[buf^1][lr][lq*4], g_dt + row*DI + dblk*32 + lq*4);
            cp16(&sx [buf^1][lr][lq*4], g_xc + row*DI + dblk*32 + lq*4);
            cp16(&sz [buf^1][lr][lq*4], g_xz + row*(size_t)(2*DI) + DI + dblk*32 + lq*4);
            cp16(&sbc[buf^1][lr][lq*4], g_bdt + row*32 + lq*4);
            cp_commit();
            cp_wait<1>();
        } else {
            cp_wait<0>();
        }
        __syncthreads();

#pragma unroll 4
        for (int i = 0; i < 16; i++){
            const float dt_c = sdt[buf][i][c];
            const float x_c  = sx[buf][i][c];
            const float4 B_c = *(const float4*)&sbc[buf][i][s*4];
            const float4 C_c = *(const float4*)&sbc[buf][i][16 + s*4];
            const float dx = dt_c*x_c;
            h0 = __expf(dt_c*A0)*h0 + dx*B_c.x;
            h1 = __expf(dt_c*A1)*h1 + dx*B_c.y;
            h2 = __expf(dt_c*A2)*h2 + dx*B_c.z;
            h3 = __expf(dt_c*A3)*h3 + dx*B_c.w;
            float y = h0*C_c.x + h1*C_c.y + h2*C_c.z + h3*C_c.w;
            y += __shfl_down_sync(0xffffffffu, y, 2, 4);
            y += __shfl_down_sync(0xffffffffu, y, 1, 4);
            if (s == 0){
                const float z_c = sz[buf][i][c];
                const float v = (y + x_c*Dpar) * (z_c / (1.f + __expf(-z_c)));
                __half hh, ll;
                split_h(v, hh, ll);
                syh[i][c] = hh;
                syl[i][c] = ll;
            }
        }
        __syncthreads();
        size_t o = (base + tile*16 + lr)*DI + dblk*32 + lq*4;
        *(uint2*)&g_yzh[o] = *(uint2*)&syh[lr][lq*4];
        *(uint2*)&g_yzl[o] = *(uint2*)&syl[lr][lq*4];
    }
}

// ===========================================================================
extern "C" void kernel_launch(void* const* d_in, const int* in_sizes, int n_in,
                              void* d_out, int out_size)
{
    const float* x      = (const float*)d_in[0];
    const float* W_in   = (const float*)d_in[1];
    const float* conv_w = (const float*)d_in[2];
    const float* conv_b = (const float*)d_in[3];
    const float* W_x    = (const float*)d_in[4];
    const float* W_dt   = (const float*)d_in[5];
    const float* b_dt   = (const float*)d_in[6];
    const float* W_out  = (const float*)d_in[7];
    const float* A_log  = (const float*)d_in[8];
    const float* D_par  = (const float*)d_in[9];
    float* out = (float*)d_out;

    float *xz, *dt;
    cudaGetSymbolAddress((void**)&xz, g_xz);
    cudaGetSymbolAddress((void**)&dt, g_dt);
    __half *xh,*xl,*xch,*xcl,*yzh,*yzl,*win,*wdt,*wout;
    cudaGetSymbolAddress((void**)&xh,  g_xh);   cudaGetSymbolAddress((void**)&xl,  g_xl);
    cudaGetSymbolAddress((void**)&xch, g_xch);  cudaGetSymbolAddress((void**)&xcl, g_xcl);
    cudaGetSymbolAddress((void**)&yzh, g_yzh);  cudaGetSymbolAddress((void**)&yzl, g_yzl);
    cudaGetSymbolAddress((void**)&win, g_win);
    cudaGetSymbolAddress((void**)&wdt, g_wdt);
    cudaGetSymbolAddress((void**)&wout,g_wout);

    cudaFuncSetAttribute(gemm_mma<0>, cudaFuncAttributeMaxDynamicSharedMemorySize, SMEM_GEMM);
    cudaFuncSetAttribute(gemm_mma<1>, cudaFuncAttributeMaxDynamicSharedMemorySize, SMEM_GEMM);

    // 0a) split x -> fp16 hi/lo
    split_kernel<<<(ROWS*DM + 255)/256, 256>>>(x, xh, xl, ROWS*DM);
    // 0b) transpose weights to [N,K] fp16
    transpose_half<<<dim3((2*DI)/32, DM/32), 256>>>(W_in,  win,  DM, 2*DI);
    transpose_half<<<dim3(DI/32,     DI/32), 256>>>(W_dt,  wdt,  DI, DI);
    transpose_half<<<dim3(DM/32,     DI/32), 256>>>(W_out, wout, DI, DM);

    // 1) xz = x @ W_in                     (8192 x 4096 x 1024)
    gemm_mma<0><<<dim3((2*DI)/128, ROWS/128), 256, SMEM_GEMM>>>(
        xh, xl, win, xz, ROWS, 2*DI, DM, nullptr);

    // 2) xc = silu(causal_dwconv(x_inner)) (+ fp16 split)
    conv_silu_kernel<<<dim3(DI/256, SEQ/8, BATCH), 256>>>(conv_w, conv_b);

    // 3) bdt = xc @ W_x                    (N = 32, fp32 CUDA cores)
    bdt_kernel<<<(ROWS/8 + 7)/8, 256>>>(W_x);

    // 4) dt = softplus(xc @ W_dt + b_dt)   (8192 x 2048 x 2048)
    gemm_mma<1><<<dim3(DI/128, ROWS/128), 256, SMEM_GEMM>>>(
        xch, xcl, wdt, dt, ROWS, DI, DI, b_dt);

    // 5) selective scan + skip + gating -> yz (fp16 hi/lo)
    scan_kernel<<<dim3(BATCH, DI/32), 128>>>(A_log, D_par);

    // 6) out = yz @ W_out                  (8192 x 1024 x 2048)
    gemm_mma<0><<<dim3(DM/128, ROWS/128), 256, SMEM_GEMM>>>(
        yzh, yzl, wout, out, ROWS, DM, DI, nullptr);
}